// round 2
// baseline (speedup 1.0000x reference)
#include <cuda_runtime.h>
#include <cuda_bf16.h>

#define BQ   65536
#define HID  256
#define NCOL 2695      // 77 heads * 35
#define TM   32        // rows per CTA

// ---------------- scratch (static __device__ arrays: allowed) ----------------
__device__ float g_f[(size_t)BQ * HID];          // hidden activations (67 MB)
__device__ float g_Wt[3 * HID * HID];            // W1,W2,W3 transposed: [j][k]
__device__ float g_Wht[NCOL * HID];              // Wh transposed: [col][k]

using u64 = unsigned long long;

// packed f32x2 FMA (Blackwell FFMA2) — 2x throughput vs 3-reg FFMA
__device__ __forceinline__ void fma2(u64 &d, u64 a, u64 b) {
    asm("fma.rn.f32x2 %0, %1, %2, %0;" : "+l"(d) : "l"(a), "l"(b));
}
__device__ __forceinline__ float psum(u64 v) {
    return __int_as_float((unsigned)v) + __int_as_float((unsigned)(v >> 32));
}
__device__ __forceinline__ float silu(float v) {
    return v / (1.f + __expf(-v));
}

// ---------------- weight transposes (tiny) ----------------
__global__ void transpose_hidden_k(const float* __restrict__ W1,
                                   const float* __restrict__ W2,
                                   const float* __restrict__ W3) {
    int i = blockIdx.x * blockDim.x + threadIdx.x;
    if (i >= 3 * HID * HID) return;
    int l   = i >> 16;
    int rem = i & 65535;
    int jj  = rem >> 8;     // output column
    int k   = rem & 255;    // k index
    const float* W = (l == 0) ? W1 : (l == 1) ? W2 : W3;
    g_Wt[i] = W[k * HID + jj];
}

__global__ void transpose_head_k(const float* __restrict__ Wh) {
    int i = blockIdx.x * blockDim.x + threadIdx.x;
    if (i >= NCOL * HID) return;
    int c = i >> 8;
    int k = i & 255;
    g_Wht[i] = Wh[k * NCOL + c];
}

// ---------------- hidden layers: x(7) -> 256 -> 256 -> 256 -> 256 ----------------
__global__ __launch_bounds__(HID)
void hidden_kernel(const float* __restrict__ x,
                   const float* __restrict__ W0, const float* __restrict__ b0,
                   const float* __restrict__ b1, const float* __restrict__ b2,
                   const float* __restrict__ b3) {
    __shared__ __align__(16) float hs[TM * HID];   // 32 KB activation tile
    __shared__ float xs[TM * 8];

    const int j    = threadIdx.x;        // feature/column owned by this thread
    const int row0 = blockIdx.x * TM;

    // stage x tile
    for (int i = j; i < TM * 7; i += HID) {
        int r = i / 7, c = i % 7;
        xs[r * 8 + c] = x[(size_t)(row0 + r) * 7 + c];
    }
    __syncthreads();

    // layer 0 : K = 7 (plain fp32)
    {
        float acc[TM];
#pragma unroll
        for (int r = 0; r < TM; r++) acc[r] = 0.f;
#pragma unroll
        for (int k = 0; k < 7; k++) {
            float w = W0[k * HID + j];
#pragma unroll
            for (int r = 0; r < TM; r++) acc[r] += xs[r * 8 + k] * w;
        }
        float bb = b0[j];
#pragma unroll
        for (int r = 0; r < TM; r++) hs[r * HID + j] = silu(acc[r] + bb);
    }
    __syncthreads();

    const float* bias[3] = {b1, b2, b3};

    for (int l = 0; l < 3; l++) {
        u64 acc[TM];
#pragma unroll
        for (int r = 0; r < TM; r++) acc[r] = 0ull;

        const ulonglong2* wr =
            reinterpret_cast<const ulonglong2*>(g_Wt + l * HID * HID + j * HID);

#pragma unroll 2
        for (int k4 = 0; k4 < HID / 4; k4++) {
            ulonglong2 w = wr[k4];                       // 4 weights (2 f32x2 pairs)
#pragma unroll
            for (int r = 0; r < TM; r++) {
                ulonglong2 h =
                    reinterpret_cast<const ulonglong2*>(hs + r * HID)[k4]; // LDS.128 broadcast
                fma2(acc[r], h.x, w.x);
                fma2(acc[r], h.y, w.y);
            }
        }

        float bb = bias[l][j];
        __syncthreads();                 // everyone done reading hs
        if (l < 2) {
#pragma unroll
            for (int r = 0; r < TM; r++) hs[r * HID + j] = silu(psum(acc[r]) + bb);
            __syncthreads();
        } else {
#pragma unroll
            for (int r = 0; r < TM; r++)
                g_f[(size_t)(row0 + r) * HID + j] = silu(psum(acc[r]) + bb);
        }
    }
}

// ---------------- head GEMM + scale epilogue ----------------
__global__ __launch_bounds__(HID)
void head_kernel(const float* __restrict__ x,
                 const float* __restrict__ bh,
                 float* __restrict__ out) {
    __shared__ __align__(16) float fs[TM * HID];   // 32 KB hidden tile
    __shared__ float sL[TM], sR[TM], sN[TM];

    const int j    = threadIdx.x;
    const int row0 = blockIdx.x * TM;

    // stage hidden activations (coalesced)
#pragma unroll
    for (int r = 0; r < TM; r++)
        fs[r * HID + j] = g_f[(size_t)(row0 + r) * HID + j];

    // per-row profiles
    if (j < TM) {
        float lam = x[(size_t)(row0 + j) * 7];                 // x[:,0]
        float s   = 1.f / (1.f + __expf(-lam * (5.0f / 0.15f)));
        sL[j] = 1.f - s;
        sR[j] = s;
        sN[j] = __expf(-25.f * lam * lam);                     // exp(-(lam/0.2)^2)
    }
    __syncthreads();

    const int j0 = blockIdx.y * HID + j;
    if (j0 < NCOL) {
        u64 acc[TM];
#pragma unroll
        for (int r = 0; r < TM; r++) acc[r] = 0ull;

        const ulonglong2* wr =
            reinterpret_cast<const ulonglong2*>(g_Wht + (size_t)j0 * HID);

#pragma unroll 2
        for (int k4 = 0; k4 < HID / 4; k4++) {
            ulonglong2 w = wr[k4];
#pragma unroll
            for (int r = 0; r < TM; r++) {
                ulonglong2 h =
                    reinterpret_cast<const ulonglong2*>(fs + r * HID)[k4];
                fma2(acc[r], h.x, w.x);
                fma2(acc[r], h.y, w.y);
            }
        }

        float bb   = bh[j0];
        int   head = j0 / 35;
#pragma unroll
        for (int r = 0; r < TM; r++) {
            float v  = psum(acc[r]) + bb;
            float sc = (head < 35) ? 1.f
                     : (head < 49) ? sL[r]
                     : (head < 63) ? sR[r]
                     :               sN[r];
            out[(size_t)(row0 + r) * NCOL + j0] = v * sc;
        }
    }
}

// ---------------- launch ----------------
extern "C" void kernel_launch(void* const* d_in, const int* in_sizes, int n_in,
                              void* d_out, int out_size) {
    const float* x  = (const float*)d_in[0];
    const float* W0 = (const float*)d_in[1];
    const float* b0 = (const float*)d_in[2];
    const float* W1 = (const float*)d_in[3];
    const float* b1 = (const float*)d_in[4];
    const float* W2 = (const float*)d_in[5];
    const float* b2 = (const float*)d_in[6];
    const float* W3 = (const float*)d_in[7];
    const float* b3 = (const float*)d_in[8];
    const float* Wh = (const float*)d_in[9];
    const float* bh = (const float*)d_in[10];
    float* out = (float*)d_out;

    transpose_hidden_k<<<(3 * HID * HID + 255) / 256, 256>>>(W1, W2, W3);
    transpose_head_k<<<(NCOL * HID + 255) / 256, 256>>>(Wh);

    hidden_kernel<<<BQ / TM, HID>>>(x, W0, b0, b1, b2, b3);

    dim3 grid(BQ / TM, (NCOL + HID - 1) / HID);
    head_kernel<<<grid, HID>>>(x, bh, out);
}

// round 3
// speedup vs baseline: 1.0011x; 1.0011x over previous
#include <cuda_runtime.h>
#include <cuda_bf16.h>

#define BQ   65536
#define HID  256
#define NCOL 2695      // 77 heads * 35
#define TM   32        // rows per CTA

// ---------------- scratch (static __device__ arrays: allowed) ----------------
__device__ float g_f[(size_t)BQ * HID];          // hidden activations (67 MB)
__device__ float g_Wt[3 * HID * HID];            // W1,W2,W3 transposed: [j][k]
__device__ float g_Wht[NCOL * HID];              // Wh transposed: [col][k]

using u64 = unsigned long long;

// packed f32x2 FMA (Blackwell FFMA2) — 2x throughput vs 3-reg FFMA
__device__ __forceinline__ void fma2(u64 &d, u64 a, u64 b) {
    asm("fma.rn.f32x2 %0, %1, %2, %0;" : "+l"(d) : "l"(a), "l"(b));
}
__device__ __forceinline__ float psum(u64 v) {
    return __int_as_float((unsigned)v) + __int_as_float((unsigned)(v >> 32));
}
__device__ __forceinline__ float silu(float v) {
    return v / (1.f + __expf(-v));
}

// ---------------- weight transposes (tiny) ----------------
__global__ void transpose_hidden_k(const float* __restrict__ W1,
                                   const float* __restrict__ W2,
                                   const float* __restrict__ W3) {
    int i = blockIdx.x * blockDim.x + threadIdx.x;
    if (i >= 3 * HID * HID) return;
    int l   = i >> 16;
    int rem = i & 65535;
    int jj  = rem >> 8;     // output column
    int k   = rem & 255;    // k index
    const float* W = (l == 0) ? W1 : (l == 1) ? W2 : W3;
    g_Wt[i] = W[k * HID + jj];
}

__global__ void transpose_head_k(const float* __restrict__ Wh) {
    int i = blockIdx.x * blockDim.x + threadIdx.x;
    if (i >= NCOL * HID) return;
    int c = i >> 8;
    int k = i & 255;
    g_Wht[i] = Wh[k * NCOL + c];
}

// ---------------- hidden layers: x(7) -> 256 -> 256 -> 256 -> 256 ----------------
__global__ __launch_bounds__(HID)
void hidden_kernel(const float* __restrict__ x,
                   const float* __restrict__ W0, const float* __restrict__ b0,
                   const float* __restrict__ b1, const float* __restrict__ b2,
                   const float* __restrict__ b3) {
    __shared__ __align__(16) float hs[TM * HID];   // 32 KB activation tile
    __shared__ float xs[TM * 8];

    const int j    = threadIdx.x;        // feature/column owned by this thread
    const int row0 = blockIdx.x * TM;

    // stage x tile
    for (int i = j; i < TM * 7; i += HID) {
        int r = i / 7, c = i % 7;
        xs[r * 8 + c] = x[(size_t)(row0 + r) * 7 + c];
    }
    __syncthreads();

    // layer 0 : K = 7 (plain fp32)
    {
        float acc[TM];
#pragma unroll
        for (int r = 0; r < TM; r++) acc[r] = 0.f;
#pragma unroll
        for (int k = 0; k < 7; k++) {
            float w = W0[k * HID + j];
#pragma unroll
            for (int r = 0; r < TM; r++) acc[r] += xs[r * 8 + k] * w;
        }
        float bb = b0[j];
#pragma unroll
        for (int r = 0; r < TM; r++) hs[r * HID + j] = silu(acc[r] + bb);
    }
    __syncthreads();

    const float* bias[3] = {b1, b2, b3};

    for (int l = 0; l < 3; l++) {
        u64 acc[TM];
#pragma unroll
        for (int r = 0; r < TM; r++) acc[r] = 0ull;

        const ulonglong2* wr =
            reinterpret_cast<const ulonglong2*>(g_Wt + l * HID * HID + j * HID);

#pragma unroll 2
        for (int k4 = 0; k4 < HID / 4; k4++) {
            ulonglong2 w = wr[k4];                       // 4 weights (2 f32x2 pairs)
#pragma unroll
            for (int r = 0; r < TM; r++) {
                ulonglong2 h =
                    reinterpret_cast<const ulonglong2*>(hs + r * HID)[k4]; // LDS.128 broadcast
                fma2(acc[r], h.x, w.x);
                fma2(acc[r], h.y, w.y);
            }
        }

        float bb = bias[l][j];
        __syncthreads();                 // everyone done reading hs
        if (l < 2) {
#pragma unroll
            for (int r = 0; r < TM; r++) hs[r * HID + j] = silu(psum(acc[r]) + bb);
            __syncthreads();
        } else {
#pragma unroll
            for (int r = 0; r < TM; r++)
                g_f[(size_t)(row0 + r) * HID + j] = silu(psum(acc[r]) + bb);
        }
    }
}

// ---------------- head GEMM + scale epilogue ----------------
__global__ __launch_bounds__(HID)
void head_kernel(const float* __restrict__ x,
                 const float* __restrict__ bh,
                 float* __restrict__ out) {
    __shared__ __align__(16) float fs[TM * HID];   // 32 KB hidden tile
    __shared__ float sL[TM], sR[TM], sN[TM];

    const int j    = threadIdx.x;
    const int row0 = blockIdx.x * TM;

    // stage hidden activations (coalesced)
#pragma unroll
    for (int r = 0; r < TM; r++)
        fs[r * HID + j] = g_f[(size_t)(row0 + r) * HID + j];

    // per-row profiles
    if (j < TM) {
        float lam = x[(size_t)(row0 + j) * 7];                 // x[:,0]
        float s   = 1.f / (1.f + __expf(-lam * (5.0f / 0.15f)));
        sL[j] = 1.f - s;
        sR[j] = s;
        sN[j] = __expf(-25.f * lam * lam);                     // exp(-(lam/0.2)^2)
    }
    __syncthreads();

    const int j0 = blockIdx.y * HID + j;
    if (j0 < NCOL) {
        u64 acc[TM];
#pragma unroll
        for (int r = 0; r < TM; r++) acc[r] = 0ull;

        const ulonglong2* wr =
            reinterpret_cast<const ulonglong2*>(g_Wht + (size_t)j0 * HID);

#pragma unroll 2
        for (int k4 = 0; k4 < HID / 4; k4++) {
            ulonglong2 w = wr[k4];
#pragma unroll
            for (int r = 0; r < TM; r++) {
                ulonglong2 h =
                    reinterpret_cast<const ulonglong2*>(fs + r * HID)[k4];
                fma2(acc[r], h.x, w.x);
                fma2(acc[r], h.y, w.y);
            }
        }

        float bb   = bh[j0];
        int   head = j0 / 35;
#pragma unroll
        for (int r = 0; r < TM; r++) {
            float v  = psum(acc[r]) + bb;
            float sc = (head < 35) ? 1.f
                     : (head < 49) ? sL[r]
                     : (head < 63) ? sR[r]
                     :               sN[r];
            out[(size_t)(row0 + r) * NCOL + j0] = v * sc;
        }
    }
}

// ---------------- launch ----------------
extern "C" void kernel_launch(void* const* d_in, const int* in_sizes, int n_in,
                              void* d_out, int out_size) {
    const float* x  = (const float*)d_in[0];
    const float* W0 = (const float*)d_in[1];
    const float* b0 = (const float*)d_in[2];
    const float* W1 = (const float*)d_in[3];
    const float* b1 = (const float*)d_in[4];
    const float* W2 = (const float*)d_in[5];
    const float* b2 = (const float*)d_in[6];
    const float* W3 = (const float*)d_in[7];
    const float* b3 = (const float*)d_in[8];
    const float* Wh = (const float*)d_in[9];
    const float* bh = (const float*)d_in[10];
    float* out = (float*)d_out;

    transpose_hidden_k<<<(3 * HID * HID + 255) / 256, 256>>>(W1, W2, W3);
    transpose_head_k<<<(NCOL * HID + 255) / 256, 256>>>(Wh);

    hidden_kernel<<<BQ / TM, HID>>>(x, W0, b0, b1, b2, b3);

    dim3 grid(BQ / TM, (NCOL + HID - 1) / HID);
    head_kernel<<<grid, HID>>>(x, bh, out);
}

// round 4
// speedup vs baseline: 1.0082x; 1.0071x over previous
#include <cuda_runtime.h>
#include <cuda_bf16.h>

#define BQ   65536
#define HID  256
#define NCOL 2695      // 77 heads * 35

// ---------------- scratch ----------------
__device__ float g_f[(size_t)BQ * HID];          // hidden activations (67 MB, L2-resident)
__device__ float g_Wt[3 * HID * HID];            // W1,W2,W3 transposed: [col][k]
__device__ float g_Wht[NCOL * HID];              // Wh transposed: [col][k]

using u64 = unsigned long long;

__device__ __forceinline__ void fma2(u64 &d, u64 a, u64 b) {
    asm("fma.rn.f32x2 %0, %1, %2, %0;" : "+l"(d) : "l"(a), "l"(b));
}
__device__ __forceinline__ float psum(u64 v) {
    return __int_as_float((unsigned)v) + __int_as_float((unsigned)(v >> 32));
}
__device__ __forceinline__ float silu(float v) {
    return v / (1.f + __expf(-v));
}

// ---------------- weight transposes (tiny) ----------------
__global__ void transpose_hidden_k(const float* __restrict__ W1,
                                   const float* __restrict__ W2,
                                   const float* __restrict__ W3) {
    int i = blockIdx.x * blockDim.x + threadIdx.x;
    if (i >= 3 * HID * HID) return;
    int l   = i >> 16;
    int rem = i & 65535;
    int jj  = rem >> 8;
    int k   = rem & 255;
    const float* W = (l == 0) ? W1 : (l == 1) ? W2 : W3;
    g_Wt[i] = W[k * HID + jj];
}

__global__ void transpose_head_k(const float* __restrict__ Wh) {
    int i = blockIdx.x * blockDim.x + threadIdx.x;
    if (i >= NCOL * HID) return;
    int c = i >> 8;
    int k = i & 255;
    g_Wht[i] = Wh[k * NCOL + c];
}

// ---------------- hidden layers: 32 rows x 256 cols per CTA ----------------
// 256 threads: thread t -> rows [(t>>7)*16, +16), cols {t&127, (t&127)+128}
__global__ __launch_bounds__(256)
void hidden_kernel(const float* __restrict__ x,
                   const float* __restrict__ W0, const float* __restrict__ b0,
                   const float* __restrict__ b1, const float* __restrict__ b2,
                   const float* __restrict__ b3) {
    __shared__ __align__(16) float hs[32 * HID];   // 32 KB
    __shared__ float xs[32 * 8];

    const int t    = threadIdx.x;
    const int r0   = (t >> 7) * 16;          // 0 or 16 (warp-uniform)
    const int c0   = t & 127;
    const int c1   = c0 + 128;
    const int row0 = blockIdx.x * 32;

    // stage x tile
    for (int i = t; i < 32 * 7; i += 256) {
        int r = i / 7, c = i % 7;
        xs[r * 8 + c] = x[(size_t)(row0 + r) * 7 + c];
    }
    __syncthreads();

    // layer 0 : K = 7
    {
        float a0[16], a1[16];
#pragma unroll
        for (int r = 0; r < 16; r++) { a0[r] = 0.f; a1[r] = 0.f; }
#pragma unroll
        for (int k = 0; k < 7; k++) {
            float w0 = W0[k * HID + c0];
            float w1 = W0[k * HID + c1];
#pragma unroll
            for (int r = 0; r < 16; r++) {
                float xv = xs[(r0 + r) * 8 + k];
                a0[r] += xv * w0;
                a1[r] += xv * w1;
            }
        }
        float bb0 = b0[c0], bb1 = b0[c1];
#pragma unroll
        for (int r = 0; r < 16; r++) {
            hs[(r0 + r) * HID + c0] = silu(a0[r] + bb0);
            hs[(r0 + r) * HID + c1] = silu(a1[r] + bb1);
        }
    }
    __syncthreads();

    const float* bias[3] = {b1, b2, b3};

    for (int l = 0; l < 3; l++) {
        u64 acc0[16], acc1[16];
#pragma unroll
        for (int r = 0; r < 16; r++) { acc0[r] = 0ull; acc1[r] = 0ull; }

        const ulonglong2* w0p =
            reinterpret_cast<const ulonglong2*>(g_Wt + l * HID * HID + c0 * HID);
        const ulonglong2* w1p =
            reinterpret_cast<const ulonglong2*>(g_Wt + l * HID * HID + c1 * HID);

#pragma unroll 2
        for (int k4 = 0; k4 < HID / 4; k4++) {
            ulonglong2 wa = w0p[k4];                 // 4 weights col c0
            ulonglong2 wb = w1p[k4];                 // 4 weights col c1
#pragma unroll
            for (int r = 0; r < 16; r++) {
                ulonglong2 h =
                    reinterpret_cast<const ulonglong2*>(hs + (r0 + r) * HID)[k4];
                fma2(acc0[r], h.x, wa.x);
                fma2(acc0[r], h.y, wa.y);
                fma2(acc1[r], h.x, wb.x);
                fma2(acc1[r], h.y, wb.y);
            }
        }

        float bb0 = bias[l][c0], bb1 = bias[l][c1];
        __syncthreads();
        if (l < 2) {
#pragma unroll
            for (int r = 0; r < 16; r++) {
                hs[(r0 + r) * HID + c0] = silu(psum(acc0[r]) + bb0);
                hs[(r0 + r) * HID + c1] = silu(psum(acc1[r]) + bb1);
            }
            __syncthreads();
        } else {
#pragma unroll
            for (int r = 0; r < 16; r++) {
                g_f[(size_t)(row0 + r0 + r) * HID + c0] = silu(psum(acc0[r]) + bb0);
                g_f[(size_t)(row0 + r0 + r) * HID + c1] = silu(psum(acc1[r]) + bb1);
            }
        }
    }
}

// ---------------- head GEMM: 16 rows x 512 cols per CTA ----------------
// 256 threads: thread t -> all 16 rows, cols {base+t, base+t+256}
__global__ __launch_bounds__(256)
void head_kernel(const float* __restrict__ x,
                 const float* __restrict__ bh,
                 float* __restrict__ out) {
    __shared__ __align__(16) float fs[16 * HID];   // 16 KB
    __shared__ float sL[16], sR[16], sN[16];

    const int t    = threadIdx.x;
    const int row0 = blockIdx.x * 16;
    const int base = blockIdx.y * 512;
    const int c0   = base + t;
    const int c1   = c0 + 256;
    const bool v0  = (c0 < NCOL);
    const bool v1  = (c1 < NCOL);

    // stage hidden activations (coalesced)
#pragma unroll
    for (int r = 0; r < 16; r++)
        fs[r * HID + t] = g_f[(size_t)(row0 + r) * HID + t];

    // per-row profiles
    if (t < 16) {
        float lam = x[(size_t)(row0 + t) * 7];
        float s   = 1.f / (1.f + __expf(-lam * (5.0f / 0.15f)));
        sL[t] = 1.f - s;
        sR[t] = s;
        sN[t] = __expf(-25.f * lam * lam);
    }
    __syncthreads();

    u64 acc0[16], acc1[16];
#pragma unroll
    for (int r = 0; r < 16; r++) { acc0[r] = 0ull; acc1[r] = 0ull; }

    // clamp OOB columns to col 0 (wasted but safe work; stores are guarded)
    const ulonglong2* w0p =
        reinterpret_cast<const ulonglong2*>(g_Wht + (size_t)(v0 ? c0 : 0) * HID);
    const ulonglong2* w1p =
        reinterpret_cast<const ulonglong2*>(g_Wht + (size_t)(v1 ? c1 : 0) * HID);

#pragma unroll 2
    for (int k4 = 0; k4 < HID / 4; k4++) {
        ulonglong2 wa = w0p[k4];
        ulonglong2 wb = w1p[k4];
#pragma unroll
        for (int r = 0; r < 16; r++) {
            ulonglong2 h =
                reinterpret_cast<const ulonglong2*>(fs + r * HID)[k4];
            fma2(acc0[r], h.x, wa.x);
            fma2(acc0[r], h.y, wa.y);
            fma2(acc1[r], h.x, wb.x);
            fma2(acc1[r], h.y, wb.y);
        }
    }

    if (v0) {
        float bb   = bh[c0];
        int   head = c0 / 35;
#pragma unroll
        for (int r = 0; r < 16; r++) {
            float v  = psum(acc0[r]) + bb;
            float sc = (head < 35) ? 1.f
                     : (head < 49) ? sL[r]
                     : (head < 63) ? sR[r]
                     :               sN[r];
            out[(size_t)(row0 + r) * NCOL + c0] = v * sc;
        }
    }
    if (v1) {
        float bb   = bh[c1];
        int   head = c1 / 35;
#pragma unroll
        for (int r = 0; r < 16; r++) {
            float v  = psum(acc1[r]) + bb;
            float sc = (head < 35) ? 1.f
                     : (head < 49) ? sL[r]
                     : (head < 63) ? sR[r]
                     :               sN[r];
            out[(size_t)(row0 + r) * NCOL + c1] = v * sc;
        }
    }
}

// ---------------- launch ----------------
extern "C" void kernel_launch(void* const* d_in, const int* in_sizes, int n_in,
                              void* d_out, int out_size) {
    const float* x  = (const float*)d_in[0];
    const float* W0 = (const float*)d_in[1];
    const float* b0 = (const float*)d_in[2];
    const float* W1 = (const float*)d_in[3];
    const float* b1 = (const float*)d_in[4];
    const float* W2 = (const float*)d_in[5];
    const float* b2 = (const float*)d_in[6];
    const float* W3 = (const float*)d_in[7];
    const float* b3 = (const float*)d_in[8];
    const float* Wh = (const float*)d_in[9];
    const float* bh = (const float*)d_in[10];
    float* out = (float*)d_out;

    transpose_hidden_k<<<(3 * HID * HID + 255) / 256, 256>>>(W1, W2, W3);
    transpose_head_k<<<(NCOL * HID + 255) / 256, 256>>>(Wh);

    hidden_kernel<<<BQ / 32, 256>>>(x, W0, b0, b1, b2, b3);

    dim3 grid(BQ / 16, (NCOL + 511) / 512);
    head_kernel<<<grid, 256>>>(x, bh, out);
}

// round 5
// speedup vs baseline: 3.3692x; 3.3418x over previous
#include <cuda_runtime.h>
#include <cuda_bf16.h>
#include <cstdint>

#define BQ   65536
#define HID  256
#define NCOL 2695
#define NPAD 2816           // 22 * 128
#define KSTRIDE 40          // 32 k + 8 pad bf16  (80B row = 5*16B, ldmatrix conflict-free)

typedef __nv_bfloat16 bf16;

// ---------------- scratch ----------------
__device__ bf16 g_a_hi[(size_t)BQ * HID], g_a_lo[(size_t)BQ * HID];   // ping
__device__ bf16 g_b_hi[(size_t)BQ * HID], g_b_lo[(size_t)BQ * HID];   // pong
__device__ bf16 g_w_hi[3 * HID * HID],  g_w_lo[3 * HID * HID];        // W1..W3, [l][n][k]
__device__ bf16 g_wh_hi[NPAD * HID],    g_wh_lo[NPAD * HID];          // Wh padded, [n][k]

// ---------------- helpers ----------------
__device__ __forceinline__ uint32_t s2u(const void* p) {
    return (uint32_t)__cvta_generic_to_shared(p);
}
__device__ __forceinline__ void ldsm4(uint32_t& r0, uint32_t& r1, uint32_t& r2, uint32_t& r3,
                                      uint32_t addr) {
    asm volatile("ldmatrix.sync.aligned.m8n8.x4.shared.b16 {%0,%1,%2,%3}, [%4];"
                 : "=r"(r0), "=r"(r1), "=r"(r2), "=r"(r3) : "r"(addr));
}
__device__ __forceinline__ void mma16816(float* d,
                                         uint32_t a0, uint32_t a1, uint32_t a2, uint32_t a3,
                                         uint32_t b0, uint32_t b1) {
    asm volatile(
        "mma.sync.aligned.m16n8k16.row.col.f32.bf16.bf16.f32 "
        "{%0,%1,%2,%3},{%4,%5,%6,%7},{%8,%9},{%0,%1,%2,%3};"
        : "+f"(d[0]), "+f"(d[1]), "+f"(d[2]), "+f"(d[3])
        : "r"(a0), "r"(a1), "r"(a2), "r"(a3), "r"(b0), "r"(b1));
}
__device__ __forceinline__ float silu(float v) { return v / (1.f + __expf(-v)); }

__device__ __forceinline__ void store_split(bf16* Ohi, bf16* Olo, size_t off,
                                            float v0, float v1) {
    bf16 h0 = __float2bfloat16(v0), h1 = __float2bfloat16(v1);
    __nv_bfloat162 hh; hh.x = h0; hh.y = h1;
    *(__nv_bfloat162*)(Ohi + off) = hh;
    __nv_bfloat162 ll;
    ll.x = __float2bfloat16(v0 - __bfloat162float(h0));
    ll.y = __float2bfloat16(v1 - __bfloat162float(h1));
    *(__nv_bfloat162*)(Olo + off) = ll;
}

// ---------------- weight prep (split to hi/lo bf16, transpose to [n][k]) ----------------
__global__ void prep_w_hidden(const float* __restrict__ W1, const float* __restrict__ W2,
                              const float* __restrict__ W3) {
    int i = blockIdx.x * 256 + threadIdx.x;
    if (i >= 3 * HID * HID) return;
    int l = i >> 16, rem = i & 65535, n = rem >> 8, k = rem & 255;
    const float* W = (l == 0) ? W1 : (l == 1) ? W2 : W3;
    float v = W[k * HID + n];
    bf16 h = __float2bfloat16(v);
    g_w_hi[i] = h;
    g_w_lo[i] = __float2bfloat16(v - __bfloat162float(h));
}

__global__ void prep_w_head(const float* __restrict__ Wh) {
    int i = blockIdx.x * 256 + threadIdx.x;
    if (i >= NPAD * HID) return;
    int n = i >> 8, k = i & 255;
    float v = (n < NCOL) ? Wh[k * NCOL + n] : 0.f;
    bf16 h = __float2bfloat16(v);
    g_wh_hi[i] = h;
    g_wh_lo[i] = __float2bfloat16(v - __bfloat162float(h));
}

// ---------------- layer 0 : silu(x @ W0 + b0), K = 7 ----------------
__global__ __launch_bounds__(256)
void layer0_kernel(const float* __restrict__ x, const float* __restrict__ W0,
                   const float* __restrict__ b0) {
    const int t = threadIdx.x;
    const int row0 = blockIdx.x * 16;
    float w[7];
#pragma unroll
    for (int k = 0; k < 7; k++) w[k] = W0[k * HID + t];
    float bb = b0[t];
    __shared__ float xs[16 * 8];
    for (int i = t; i < 16 * 7; i += 256) {
        int r = i / 7, c = i % 7;
        xs[r * 8 + c] = x[(size_t)(row0 + r) * 7 + c];
    }
    __syncthreads();
#pragma unroll
    for (int r = 0; r < 16; r++) {
        float acc = bb;
#pragma unroll
        for (int k = 0; k < 7; k++) acc += xs[r * 8 + k] * w[k];
        float s = silu(acc);
        bf16 h = __float2bfloat16(s);
        size_t o = (size_t)(row0 + r) * HID + t;
        g_a_hi[o] = h;
        g_a_lo[o] = __float2bfloat16(s - __bfloat162float(h));
    }
}

// ---------------- shared mainloop: 128x128 CTA tile, K=256, split-bf16 x3 MMA ----------------
__device__ __forceinline__ void gemm_mainloop(
    const bf16* __restrict__ Ahi, const bf16* __restrict__ Alo,   // at row0, [.][256]
    const bf16* __restrict__ Bhi, const bf16* __restrict__ Blo,   // at nb0,  [.][256]
    bf16* As_hi, bf16* As_lo, bf16* Bs_hi, bf16* Bs_lo,
    float acc[2][4][2][4], int t)
{
    const int lane = t & 31, wid = t >> 5;
    const int wm = wid & 3, wn = wid >> 2;

    for (int kc = 0; kc < 8; kc++) {
        const int k0 = kc * 32;
        // ---- stage 128x32 tiles of A(hi,lo) and B(hi,lo), coalesced ----
#pragma unroll
        for (int i = 0; i < 2; i++) {
            int u = t + i * 256;           // 0..511
            int r = u >> 2, c = u & 3;     // row, 16B-chunk
            *(uint4*)(As_hi + r * KSTRIDE + c * 8) = *(const uint4*)(Ahi + (size_t)r * HID + k0 + c * 8);
            *(uint4*)(As_lo + r * KSTRIDE + c * 8) = *(const uint4*)(Alo + (size_t)r * HID + k0 + c * 8);
            *(uint4*)(Bs_hi + r * KSTRIDE + c * 8) = *(const uint4*)(Bhi + (size_t)r * HID + k0 + c * 8);
            *(uint4*)(Bs_lo + r * KSTRIDE + c * 8) = *(const uint4*)(Blo + (size_t)r * HID + k0 + c * 8);
        }
        __syncthreads();

#pragma unroll
        for (int kk = 0; kk < 2; kk++) {
            const int kfo = kk * 16 + ((lane >> 4) << 3);
            // A fragments (2 m-tiles x hi/lo)
            uint32_t ah[2][4], al[2][4];
#pragma unroll
            for (int mt = 0; mt < 2; mt++) {
                int row = wm * 32 + mt * 16 + (lane & 15);
                ldsm4(ah[mt][0], ah[mt][1], ah[mt][2], ah[mt][3], s2u(As_hi + row * KSTRIDE + kfo));
                ldsm4(al[mt][0], al[mt][1], al[mt][2], al[mt][3], s2u(As_lo + row * KSTRIDE + kfo));
            }
#pragma unroll
            for (int np = 0; np < 4; np++) {
                int nr = wn * 64 + np * 16 + (lane & 15);
                uint32_t bh4[4], bl4[4];
                ldsm4(bh4[0], bh4[1], bh4[2], bh4[3], s2u(Bs_hi + nr * KSTRIDE + kfo));
                ldsm4(bl4[0], bl4[1], bl4[2], bl4[3], s2u(Bs_lo + nr * KSTRIDE + kfo));
#pragma unroll
                for (int mt = 0; mt < 2; mt++) {
#pragma unroll
                    for (int sub = 0; sub < 2; sub++) {
                        float* d = acc[mt][np][sub];
                        uint32_t b0h = sub ? bh4[1] : bh4[0], b1h = sub ? bh4[3] : bh4[2];
                        uint32_t b0l = sub ? bl4[1] : bl4[0], b1l = sub ? bl4[3] : bl4[2];
                        mma16816(d, ah[mt][0], ah[mt][1], ah[mt][2], ah[mt][3], b0h, b1h);
                        mma16816(d, ah[mt][0], ah[mt][1], ah[mt][2], ah[mt][3], b0l, b1l);
                        mma16816(d, al[mt][0], al[mt][1], al[mt][2], al[mt][3], b0h, b1h);
                    }
                }
            }
        }
        __syncthreads();
    }
}

// ---------------- hidden GEMM: silu epilogue, writes split-bf16 ----------------
// SRC=0: g_a -> g_b ; SRC=1: g_b -> g_a ; SRC=2: g_a -> g_b
template <int L>
__global__ __launch_bounds__(256)
void gemm_hidden(const float* __restrict__ bias) {
    __shared__ bf16 As_hi[128 * KSTRIDE], As_lo[128 * KSTRIDE];
    __shared__ bf16 Bs_hi[128 * KSTRIDE], Bs_lo[128 * KSTRIDE];

    const int t    = threadIdx.x;
    const int row0 = blockIdx.x * 128;
    const int nb0  = blockIdx.y * 128;

    const bf16* Ahi = (L == 1 ? g_b_hi : g_a_hi) + (size_t)row0 * HID;
    const bf16* Alo = (L == 1 ? g_b_lo : g_a_lo) + (size_t)row0 * HID;
    bf16* Ohi = (L == 1 ? g_a_hi : g_b_hi);
    bf16* Olo = (L == 1 ? g_a_lo : g_b_lo);
    const bf16* Bhi = g_w_hi + (size_t)L * HID * HID + (size_t)nb0 * HID;
    const bf16* Blo = g_w_lo + (size_t)L * HID * HID + (size_t)nb0 * HID;

    float acc[2][4][2][4];
#pragma unroll
    for (int a = 0; a < 2; a++)
#pragma unroll
        for (int b = 0; b < 4; b++)
#pragma unroll
            for (int c = 0; c < 2; c++)
#pragma unroll
                for (int d = 0; d < 4; d++) acc[a][b][c][d] = 0.f;

    gemm_mainloop(Ahi, Alo, Bhi, Blo, As_hi, As_lo, Bs_hi, Bs_lo, acc, t);

    const int lane = t & 31, wid = t >> 5, wm = wid & 3, wn = wid >> 2;
#pragma unroll
    for (int mt = 0; mt < 2; mt++) {
#pragma unroll
        for (int np = 0; np < 4; np++) {
#pragma unroll
            for (int sub = 0; sub < 2; sub++) {
                float* d = acc[mt][np][sub];
                int col = nb0 + wn * 64 + np * 16 + sub * 8 + (lane & 3) * 2;
                int r   = row0 + wm * 32 + mt * 16 + (lane >> 2);
                float bb0 = bias[col], bb1 = bias[col + 1];
                store_split(Ohi, Olo, (size_t)r * HID + col,
                            silu(d[0] + bb0), silu(d[1] + bb1));
                store_split(Ohi, Olo, (size_t)(r + 8) * HID + col,
                            silu(d[2] + bb0), silu(d[3] + bb1));
            }
        }
    }
}

// ---------------- head GEMM: bias + lambda-profile scale epilogue, f32 out ----------------
__global__ __launch_bounds__(256)
void gemm_head(const float* __restrict__ x, const float* __restrict__ bh,
               float* __restrict__ out) {
    __shared__ bf16 As_hi[128 * KSTRIDE], As_lo[128 * KSTRIDE];
    __shared__ bf16 Bs_hi[128 * KSTRIDE], Bs_lo[128 * KSTRIDE];
    __shared__ float sL[128], sR[128], sN[128];

    const int t    = threadIdx.x;
    const int row0 = blockIdx.x * 128;
    const int nb0  = blockIdx.y * 128;

    if (t < 128) {
        float lam = x[(size_t)(row0 + t) * 7];
        float s   = 1.f / (1.f + __expf(-lam * (5.0f / 0.15f)));
        sL[t] = 1.f - s;
        sR[t] = s;
        sN[t] = __expf(-25.f * lam * lam);
    }

    const bf16* Ahi = g_b_hi + (size_t)row0 * HID;
    const bf16* Alo = g_b_lo + (size_t)row0 * HID;
    const bf16* Bhi = g_wh_hi + (size_t)nb0 * HID;
    const bf16* Blo = g_wh_lo + (size_t)nb0 * HID;

    float acc[2][4][2][4];
#pragma unroll
    for (int a = 0; a < 2; a++)
#pragma unroll
        for (int b = 0; b < 4; b++)
#pragma unroll
            for (int c = 0; c < 2; c++)
#pragma unroll
                for (int d = 0; d < 4; d++) acc[a][b][c][d] = 0.f;

    gemm_mainloop(Ahi, Alo, Bhi, Blo, As_hi, As_lo, Bs_hi, Bs_lo, acc, t);

    const int lane = t & 31, wid = t >> 5, wm = wid & 3, wn = wid >> 2;
#pragma unroll
    for (int mt = 0; mt < 2; mt++) {
#pragma unroll
        for (int np = 0; np < 4; np++) {
#pragma unroll
            for (int sub = 0; sub < 2; sub++) {
                float* d = acc[mt][np][sub];
                int col = nb0 + wn * 64 + np * 16 + sub * 8 + (lane & 3) * 2;
                int rl  = wm * 32 + mt * 16 + (lane >> 2);
                int rg  = row0 + rl;
                if (col < NCOL) {
                    float bb = bh[col];
                    int   h  = col / 35;
                    float s0 = (h < 35) ? 1.f : (h < 49) ? sL[rl]     : (h < 63) ? sR[rl]     : sN[rl];
                    float s1 = (h < 35) ? 1.f : (h < 49) ? sL[rl + 8] : (h < 63) ? sR[rl + 8] : sN[rl + 8];
                    out[(size_t)rg * NCOL + col]       = (d[0] + bb) * s0;
                    out[(size_t)(rg + 8) * NCOL + col] = (d[2] + bb) * s1;
                }
                int col1 = col + 1;
                if (col1 < NCOL) {
                    float bb = bh[col1];
                    int   h  = col1 / 35;
                    float s0 = (h < 35) ? 1.f : (h < 49) ? sL[rl]     : (h < 63) ? sR[rl]     : sN[rl];
                    float s1 = (h < 35) ? 1.f : (h < 49) ? sL[rl + 8] : (h < 63) ? sR[rl + 8] : sN[rl + 8];
                    out[(size_t)rg * NCOL + col1]       = (d[1] + bb) * s0;
                    out[(size_t)(rg + 8) * NCOL + col1] = (d[3] + bb) * s1;
                }
            }
        }
    }
}

// ---------------- launch ----------------
extern "C" void kernel_launch(void* const* d_in, const int* in_sizes, int n_in,
                              void* d_out, int out_size) {
    const float* x  = (const float*)d_in[0];
    const float* W0 = (const float*)d_in[1];
    const float* b0 = (const float*)d_in[2];
    const float* W1 = (const float*)d_in[3];
    const float* b1 = (const float*)d_in[4];
    const float* W2 = (const float*)d_in[5];
    const float* b2 = (const float*)d_in[6];
    const float* W3 = (const float*)d_in[7];
    const float* b3 = (const float*)d_in[8];
    const float* Wh = (const float*)d_in[9];
    const float* bh = (const float*)d_in[10];
    float* out = (float*)d_out;

    prep_w_hidden<<<(3 * HID * HID + 255) / 256, 256>>>(W1, W2, W3);
    prep_w_head<<<(NPAD * HID + 255) / 256, 256>>>(Wh);
    layer0_kernel<<<BQ / 16, 256>>>(x, W0, b0);

    dim3 gh(BQ / 128, HID / 128);        // (512, 2)
    gemm_hidden<0><<<gh, 256>>>(b1);     // a -> b
    gemm_hidden<1><<<gh, 256>>>(b2);     // b -> a
    gemm_hidden<2><<<gh, 256>>>(b3);     // a -> b

    dim3 gd(BQ / 128, NPAD / 128);       // (512, 22)
    gemm_head<<<gd, 256>>>(x, bh, out);
}

// round 6
// speedup vs baseline: 3.5584x; 1.0561x over previous
#include <cuda_runtime.h>
#include <cuda_bf16.h>
#include <cstdint>

#define BQ   65536
#define HID  256
#define NCOL 2695
#define NPAD 2816           // 22 * 128
#define KSTRIDE 40          // 32 k + 8 pad bf16 (80B row, ldmatrix conflict-free)
#define TILE_ELEMS (128 * KSTRIDE)
#define STAGE_ELEMS (4 * TILE_ELEMS)                // As_hi,As_lo,Bs_hi,Bs_lo
#define SMEM_BYTES (2 * STAGE_ELEMS * sizeof(__nv_bfloat16))   // 81920

typedef __nv_bfloat16 bf16;

// ---------------- scratch ----------------
__device__ bf16 g_a_hi[(size_t)BQ * HID], g_a_lo[(size_t)BQ * HID];   // ping
__device__ bf16 g_b_hi[(size_t)BQ * HID], g_b_lo[(size_t)BQ * HID];   // pong
__device__ bf16 g_w_hi[3 * HID * HID],  g_w_lo[3 * HID * HID];        // W1..W3, [l][n][k]
__device__ bf16 g_wh_hi[NPAD * HID],    g_wh_lo[NPAD * HID];          // Wh padded, [n][k]

// ---------------- helpers ----------------
__device__ __forceinline__ uint32_t s2u(const void* p) {
    return (uint32_t)__cvta_generic_to_shared(p);
}
__device__ __forceinline__ void cp16(bf16* dst, const bf16* src) {
    asm volatile("cp.async.cg.shared.global [%0], [%1], 16;"
                 :: "r"(s2u(dst)), "l"(src));
}
__device__ __forceinline__ void cp_commit() {
    asm volatile("cp.async.commit_group;");
}
template <int N>
__device__ __forceinline__ void cp_wait() {
    asm volatile("cp.async.wait_group %0;" :: "n"(N));
}
__device__ __forceinline__ void ldsm4(uint32_t& r0, uint32_t& r1, uint32_t& r2, uint32_t& r3,
                                      uint32_t addr) {
    asm volatile("ldmatrix.sync.aligned.m8n8.x4.shared.b16 {%0,%1,%2,%3}, [%4];"
                 : "=r"(r0), "=r"(r1), "=r"(r2), "=r"(r3) : "r"(addr));
}
__device__ __forceinline__ void mma16816(float* d,
                                         uint32_t a0, uint32_t a1, uint32_t a2, uint32_t a3,
                                         uint32_t b0, uint32_t b1) {
    asm volatile(
        "mma.sync.aligned.m16n8k16.row.col.f32.bf16.bf16.f32 "
        "{%0,%1,%2,%3},{%4,%5,%6,%7},{%8,%9},{%0,%1,%2,%3};"
        : "+f"(d[0]), "+f"(d[1]), "+f"(d[2]), "+f"(d[3])
        : "r"(a0), "r"(a1), "r"(a2), "r"(a3), "r"(b0), "r"(b1));
}
__device__ __forceinline__ float silu(float v) { return v / (1.f + __expf(-v)); }

__device__ __forceinline__ void store_split(bf16* Ohi, bf16* Olo, size_t off,
                                            float v0, float v1) {
    bf16 h0 = __float2bfloat16(v0), h1 = __float2bfloat16(v1);
    __nv_bfloat162 hh; hh.x = h0; hh.y = h1;
    *(__nv_bfloat162*)(Ohi + off) = hh;
    __nv_bfloat162 ll;
    ll.x = __float2bfloat16(v0 - __bfloat162float(h0));
    ll.y = __float2bfloat16(v1 - __bfloat162float(h1));
    *(__nv_bfloat162*)(Olo + off) = ll;
}

// ---------------- weight prep ----------------
__global__ void prep_w_hidden(const float* __restrict__ W1, const float* __restrict__ W2,
                              const float* __restrict__ W3) {
    int i = blockIdx.x * 256 + threadIdx.x;
    if (i >= 3 * HID * HID) return;
    int l = i >> 16, rem = i & 65535, n = rem >> 8, k = rem & 255;
    const float* W = (l == 0) ? W1 : (l == 1) ? W2 : W3;
    float v = W[k * HID + n];
    bf16 h = __float2bfloat16(v);
    g_w_hi[i] = h;
    g_w_lo[i] = __float2bfloat16(v - __bfloat162float(h));
}

__global__ void prep_w_head(const float* __restrict__ Wh) {
    int i = blockIdx.x * 256 + threadIdx.x;
    if (i >= NPAD * HID) return;
    int n = i >> 8, k = i & 255;
    float v = (n < NCOL) ? Wh[k * NCOL + n] : 0.f;
    bf16 h = __float2bfloat16(v);
    g_wh_hi[i] = h;
    g_wh_lo[i] = __float2bfloat16(v - __bfloat162float(h));
}

// ---------------- layer 0 : silu(x @ W0 + b0), K = 7 ----------------
__global__ __launch_bounds__(256)
void layer0_kernel(const float* __restrict__ x, const float* __restrict__ W0,
                   const float* __restrict__ b0) {
    const int t = threadIdx.x;
    const int row0 = blockIdx.x * 16;
    float w[7];
#pragma unroll
    for (int k = 0; k < 7; k++) w[k] = W0[k * HID + t];
    float bb = b0[t];
    __shared__ float xs[16 * 8];
    for (int i = t; i < 16 * 7; i += 256) {
        int r = i / 7, c = i % 7;
        xs[r * 8 + c] = x[(size_t)(row0 + r) * 7 + c];
    }
    __syncthreads();
#pragma unroll
    for (int r = 0; r < 16; r++) {
        float acc = bb;
#pragma unroll
        for (int k = 0; k < 7; k++) acc += xs[r * 8 + k] * w[k];
        float s = silu(acc);
        bf16 h = __float2bfloat16(s);
        size_t o = (size_t)(row0 + r) * HID + t;
        g_a_hi[o] = h;
        g_a_lo[o] = __float2bfloat16(s - __bfloat162float(h));
    }
}

// ---------------- pipelined mainloop: 128x128 CTA tile, K=256 ----------------
// smem ring: stage s, tile q in {Ahi,Alo,Bhi,Blo}: base + (s*4+q)*TILE_ELEMS
__device__ __forceinline__ void stage_issue(
    bf16* sm, int s,
    const bf16* __restrict__ Ahi, const bf16* __restrict__ Alo,
    const bf16* __restrict__ Bhi, const bf16* __restrict__ Blo,
    int k0, int t)
{
    const int r  = t >> 1;                 // row 0..127
    const int cc = (t & 1) * 16;           // bf16 element offset of first chunk
    bf16* st = sm + s * STAGE_ELEMS;
    const size_t go = (size_t)r * HID + k0 + cc;
    const int    so = r * KSTRIDE + cc;
    cp16(st + 0 * TILE_ELEMS + so,     Ahi + go);
    cp16(st + 0 * TILE_ELEMS + so + 8, Ahi + go + 8);
    cp16(st + 1 * TILE_ELEMS + so,     Alo + go);
    cp16(st + 1 * TILE_ELEMS + so + 8, Alo + go + 8);
    cp16(st + 2 * TILE_ELEMS + so,     Bhi + go);
    cp16(st + 2 * TILE_ELEMS + so + 8, Bhi + go + 8);
    cp16(st + 3 * TILE_ELEMS + so,     Blo + go);
    cp16(st + 3 * TILE_ELEMS + so + 8, Blo + go + 8);
    cp_commit();
}

__device__ __forceinline__ void stage_compute(bf16* sm, int s, float acc[2][4][2][4], int t)
{
    const int lane = t & 31, wid = t >> 5;
    const int wm = wid & 3, wn = wid >> 2;
    bf16* As_hi = sm + (s * 4 + 0) * TILE_ELEMS;
    bf16* As_lo = sm + (s * 4 + 1) * TILE_ELEMS;
    bf16* Bs_hi = sm + (s * 4 + 2) * TILE_ELEMS;
    bf16* Bs_lo = sm + (s * 4 + 3) * TILE_ELEMS;

#pragma unroll
    for (int kk = 0; kk < 2; kk++) {
        const int kfo = kk * 16 + ((lane >> 4) << 3);
        uint32_t ah[2][4], al[2][4];
#pragma unroll
        for (int mt = 0; mt < 2; mt++) {
            int row = wm * 32 + mt * 16 + (lane & 15);
            ldsm4(ah[mt][0], ah[mt][1], ah[mt][2], ah[mt][3], s2u(As_hi + row * KSTRIDE + kfo));
            ldsm4(al[mt][0], al[mt][1], al[mt][2], al[mt][3], s2u(As_lo + row * KSTRIDE + kfo));
        }
#pragma unroll
        for (int np = 0; np < 4; np++) {
            int nr = wn * 64 + np * 16 + (lane & 15);
            uint32_t bh4[4], bl4[4];
            ldsm4(bh4[0], bh4[1], bh4[2], bh4[3], s2u(Bs_hi + nr * KSTRIDE + kfo));
            ldsm4(bl4[0], bl4[1], bl4[2], bl4[3], s2u(Bs_lo + nr * KSTRIDE + kfo));
#pragma unroll
            for (int mt = 0; mt < 2; mt++) {
#pragma unroll
                for (int sub = 0; sub < 2; sub++) {
                    float* d = acc[mt][np][sub];
                    uint32_t b0h = sub ? bh4[1] : bh4[0], b1h = sub ? bh4[3] : bh4[2];
                    uint32_t b0l = sub ? bl4[1] : bl4[0], b1l = sub ? bl4[3] : bl4[2];
                    mma16816(d, ah[mt][0], ah[mt][1], ah[mt][2], ah[mt][3], b0h, b1h);
                    mma16816(d, ah[mt][0], ah[mt][1], ah[mt][2], ah[mt][3], b0l, b1l);
                    mma16816(d, al[mt][0], al[mt][1], al[mt][2], al[mt][3], b0h, b1h);
                }
            }
        }
    }
}

__device__ __forceinline__ void gemm_mainloop(
    bf16* sm,
    const bf16* __restrict__ Ahi, const bf16* __restrict__ Alo,
    const bf16* __restrict__ Bhi, const bf16* __restrict__ Blo,
    float acc[2][4][2][4], int t)
{
    stage_issue(sm, 0, Ahi, Alo, Bhi, Blo, 0, t);
#pragma unroll 1
    for (int kc = 0; kc < 8; kc++) {
        if (kc < 7)
            stage_issue(sm, (kc + 1) & 1, Ahi, Alo, Bhi, Blo, (kc + 1) * 32, t);
        if (kc < 7) cp_wait<1>(); else cp_wait<0>();
        __syncthreads();
        stage_compute(sm, kc & 1, acc, t);
        __syncthreads();
    }
}

// ---------------- hidden GEMM ----------------
template <int L>
__global__ __launch_bounds__(256)
void gemm_hidden(const float* __restrict__ bias) {
    extern __shared__ __align__(16) bf16 sm[];

    const int t    = threadIdx.x;
    const int row0 = blockIdx.y * 128;
    const int nb0  = blockIdx.x * 128;

    const bf16* Ahi = (L == 1 ? g_b_hi : g_a_hi) + (size_t)row0 * HID;
    const bf16* Alo = (L == 1 ? g_b_lo : g_a_lo) + (size_t)row0 * HID;
    bf16* Ohi = (L == 1 ? g_a_hi : g_b_hi);
    bf16* Olo = (L == 1 ? g_a_lo : g_b_lo);
    const bf16* Bhi = g_w_hi + (size_t)L * HID * HID + (size_t)nb0 * HID;
    const bf16* Blo = g_w_lo + (size_t)L * HID * HID + (size_t)nb0 * HID;

    float acc[2][4][2][4];
#pragma unroll
    for (int a = 0; a < 2; a++)
#pragma unroll
        for (int b = 0; b < 4; b++)
#pragma unroll
            for (int c = 0; c < 2; c++)
#pragma unroll
                for (int d = 0; d < 4; d++) acc[a][b][c][d] = 0.f;

    gemm_mainloop(sm, Ahi, Alo, Bhi, Blo, acc, t);

    const int lane = t & 31, wid = t >> 5, wm = wid & 3, wn = wid >> 2;
#pragma unroll
    for (int mt = 0; mt < 2; mt++) {
#pragma unroll
        for (int np = 0; np < 4; np++) {
#pragma unroll
            for (int sub = 0; sub < 2; sub++) {
                float* d = acc[mt][np][sub];
                int col = nb0 + wn * 64 + np * 16 + sub * 8 + (lane & 3) * 2;
                int r   = row0 + wm * 32 + mt * 16 + (lane >> 2);
                float bb0 = bias[col], bb1 = bias[col + 1];
                store_split(Ohi, Olo, (size_t)r * HID + col,
                            silu(d[0] + bb0), silu(d[1] + bb1));
                store_split(Ohi, Olo, (size_t)(r + 8) * HID + col,
                            silu(d[2] + bb0), silu(d[3] + bb1));
            }
        }
    }
}

// ---------------- head GEMM ----------------
__global__ __launch_bounds__(256)
void gemm_head(const float* __restrict__ x, const float* __restrict__ bh,
               float* __restrict__ out) {
    extern __shared__ __align__(16) bf16 sm[];
    __shared__ float sL[128], sR[128], sN[128];

    const int t    = threadIdx.x;
    const int row0 = blockIdx.y * 128;     // y = row tile (512)
    const int nb0  = blockIdx.x * 128;     // x = col tile (22) -> A stays hot in L2

    if (t < 128) {
        float lam = x[(size_t)(row0 + t) * 7];
        float s   = 1.f / (1.f + __expf(-lam * (5.0f / 0.15f)));
        sL[t] = 1.f - s;
        sR[t] = s;
        sN[t] = __expf(-25.f * lam * lam);
    }

    const bf16* Ahi = g_b_hi + (size_t)row0 * HID;
    const bf16* Alo = g_b_lo + (size_t)row0 * HID;
    const bf16* Bhi = g_wh_hi + (size_t)nb0 * HID;
    const bf16* Blo = g_wh_lo + (size_t)nb0 * HID;

    float acc[2][4][2][4];
#pragma unroll
    for (int a = 0; a < 2; a++)
#pragma unroll
        for (int b = 0; b < 4; b++)
#pragma unroll
            for (int c = 0; c < 2; c++)
#pragma unroll
                for (int d = 0; d < 4; d++) acc[a][b][c][d] = 0.f;

    gemm_mainloop(sm, Ahi, Alo, Bhi, Blo, acc, t);

    const int lane = t & 31, wid = t >> 5, wm = wid & 3, wn = wid >> 2;
#pragma unroll
    for (int mt = 0; mt < 2; mt++) {
#pragma unroll
        for (int np = 0; np < 4; np++) {
#pragma unroll
            for (int sub = 0; sub < 2; sub++) {
                float* d = acc[mt][np][sub];
                int col = nb0 + wn * 64 + np * 16 + sub * 8 + (lane & 3) * 2;
                int rl  = wm * 32 + mt * 16 + (lane >> 2);
                int rg  = row0 + rl;
                if (col < NCOL) {
                    float bb = bh[col];
                    int   h  = col / 35;
                    float s0 = (h < 35) ? 1.f : (h < 49) ? sL[rl]     : (h < 63) ? sR[rl]     : sN[rl];
                    float s1 = (h < 35) ? 1.f : (h < 49) ? sL[rl + 8] : (h < 63) ? sR[rl + 8] : sN[rl + 8];
                    out[(size_t)rg * NCOL + col]       = (d[0] + bb) * s0;
                    out[(size_t)(rg + 8) * NCOL + col] = (d[2] + bb) * s1;
                }
                int col1 = col + 1;
                if (col1 < NCOL) {
                    float bb = bh[col1];
                    int   h  = col1 / 35;
                    float s0 = (h < 35) ? 1.f : (h < 49) ? sL[rl]     : (h < 63) ? sR[rl]     : sN[rl];
                    float s1 = (h < 35) ? 1.f : (h < 49) ? sL[rl + 8] : (h < 63) ? sR[rl + 8] : sN[rl + 8];
                    out[(size_t)rg * NCOL + col1]       = (d[1] + bb) * s0;
                    out[(size_t)(rg + 8) * NCOL + col1] = (d[3] + bb) * s1;
                }
            }
        }
    }
}

// ---------------- launch ----------------
extern "C" void kernel_launch(void* const* d_in, const int* in_sizes, int n_in,
                              void* d_out, int out_size) {
    const float* x  = (const float*)d_in[0];
    const float* W0 = (const float*)d_in[1];
    const float* b0 = (const float*)d_in[2];
    const float* W1 = (const float*)d_in[3];
    const float* b1 = (const float*)d_in[4];
    const float* W2 = (const float*)d_in[5];
    const float* b2 = (const float*)d_in[6];
    const float* W3 = (const float*)d_in[7];
    const float* b3 = (const float*)d_in[8];
    const float* Wh = (const float*)d_in[9];
    const float* bh = (const float*)d_in[10];
    float* out = (float*)d_out;

    static bool attr_done = false;
    if (!attr_done) {
        cudaFuncSetAttribute(gemm_hidden<0>, cudaFuncAttributeMaxDynamicSharedMemorySize, SMEM_BYTES);
        cudaFuncSetAttribute(gemm_hidden<1>, cudaFuncAttributeMaxDynamicSharedMemorySize, SMEM_BYTES);
        cudaFuncSetAttribute(gemm_hidden<2>, cudaFuncAttributeMaxDynamicSharedMemorySize, SMEM_BYTES);
        cudaFuncSetAttribute(gemm_head,      cudaFuncAttributeMaxDynamicSharedMemorySize, SMEM_BYTES);
        attr_done = true;
    }

    prep_w_hidden<<<(3 * HID * HID + 255) / 256, 256>>>(W1, W2, W3);
    prep_w_head<<<(NPAD * HID + 255) / 256, 256>>>(Wh);
    layer0_kernel<<<BQ / 16, 256>>>(x, W0, b0);

    dim3 gh(HID / 128, BQ / 128);        // (2, 512)
    gemm_hidden<0><<<gh, 256, SMEM_BYTES>>>(b1);   // a -> b
    gemm_hidden<1><<<gh, 256, SMEM_BYTES>>>(b2);   // b -> a
    gemm_hidden<2><<<gh, 256, SMEM_BYTES>>>(b3);   // a -> b

    dim3 gd(NPAD / 128, BQ / 128);       // (22, 512)
    gemm_head<<<gd, 256, SMEM_BYTES>>>(x, bh, out);
}

// round 9
// speedup vs baseline: 4.8741x; 1.3698x over previous
#include <cuda_runtime.h>
#include <cuda_bf16.h>
#include <cstdint>

#define BQ   65536
#define HID  256
#define NCOL 2695
#define NPAD 2816                 // 22 * 128
#define TILE_B  8192              // 128 rows x 64B (32 bf16 of k), SW64-swizzled
#define STAGE_B (4 * TILE_B)      // Ahi, Alo, Bhi, Blo = 32 KB
#define NSTAGE  3
#define DYN_BYTES (NSTAGE * STAGE_B)   // 96 KB

typedef __nv_bfloat16 bf16;

// ---------------- scratch ----------------
__device__ bf16 g_a_hi[(size_t)BQ * HID], g_a_lo[(size_t)BQ * HID];
__device__ bf16 g_b_hi[(size_t)BQ * HID], g_b_lo[(size_t)BQ * HID];
__device__ bf16 g_w_hi[3 * HID * HID],  g_w_lo[3 * HID * HID];     // [l][n][k]
__device__ bf16 g_wh_hi[NPAD * HID],    g_wh_lo[NPAD * HID];       // [n][k], zero-padded

// ---------------- helpers ----------------
__device__ __forceinline__ uint32_t s2u(const void* p) {
    return (uint32_t)__cvta_generic_to_shared(p);
}
__device__ __forceinline__ void cp16s(uint32_t dst, const void* src) {
    asm volatile("cp.async.cg.shared.global [%0], [%1], 16;" :: "r"(dst), "l"(src));
}
__device__ __forceinline__ void cp_commit() { asm volatile("cp.async.commit_group;"); }
template <int N> __device__ __forceinline__ void cp_wait() {
    asm volatile("cp.async.wait_group %0;" :: "n"(N));
}
__device__ __forceinline__ void ldsm4(uint32_t& r0, uint32_t& r1, uint32_t& r2, uint32_t& r3,
                                      uint32_t addr) {
    asm volatile("ldmatrix.sync.aligned.m8n8.x4.shared.b16 {%0,%1,%2,%3}, [%4];"
                 : "=r"(r0), "=r"(r1), "=r"(r2), "=r"(r3) : "r"(addr));
}
__device__ __forceinline__ void mma16816(float* d,
                                         uint32_t a0, uint32_t a1, uint32_t a2, uint32_t a3,
                                         uint32_t b0, uint32_t b1) {
    asm volatile(
        "mma.sync.aligned.m16n8k16.row.col.f32.bf16.bf16.f32 "
        "{%0,%1,%2,%3},{%4,%5,%6,%7},{%8,%9},{%0,%1,%2,%3};"
        : "+f"(d[0]), "+f"(d[1]), "+f"(d[2]), "+f"(d[3])
        : "r"(a0), "r"(a1), "r"(a2), "r"(a3), "r"(b0), "r"(b1));
}
__device__ __forceinline__ float silu(float v) { return v / (1.f + __expf(-v)); }
__device__ __forceinline__ uint32_t sw64(uint32_t o) { return o ^ ((o >> 3) & 0x30); }

__device__ __forceinline__ void store_split(bf16* Ohi, bf16* Olo, size_t off,
                                            float v0, float v1) {
    bf16 h0 = __float2bfloat16(v0), h1 = __float2bfloat16(v1);
    __nv_bfloat162 hh; hh.x = h0; hh.y = h1;
    *(__nv_bfloat162*)(Ohi + off) = hh;
    __nv_bfloat162 ll;
    ll.x = __float2bfloat16(v0 - __bfloat162float(h0));
    ll.y = __float2bfloat16(v1 - __bfloat162float(h1));
    *(__nv_bfloat162*)(Olo + off) = ll;
}

// ---------------- weight prep ----------------
__global__ void prep_w_hidden(const float* __restrict__ W1, const float* __restrict__ W2,
                              const float* __restrict__ W3) {
    int i = blockIdx.x * 256 + threadIdx.x;
    if (i >= 3 * HID * HID) return;
    int l = i >> 16, rem = i & 65535, n = rem >> 8, k = rem & 255;
    const float* W = (l == 0) ? W1 : (l == 1) ? W2 : W3;
    float v = W[k * HID + n];
    bf16 h = __float2bfloat16(v);
    g_w_hi[i] = h;
    g_w_lo[i] = __float2bfloat16(v - __bfloat162float(h));
}
__global__ void prep_w_head(const float* __restrict__ Wh) {
    int i = blockIdx.x * 256 + threadIdx.x;
    if (i >= NPAD * HID) return;
    int n = i >> 8, k = i & 255;
    float v = (n < NCOL) ? Wh[k * NCOL + n] : 0.f;
    bf16 h = __float2bfloat16(v);
    g_wh_hi[i] = h;
    g_wh_lo[i] = __float2bfloat16(v - __bfloat162float(h));
}

// ---------------- layer 0 : silu(x @ W0 + b0), K = 7 ----------------
__global__ __launch_bounds__(256)
void layer0_kernel(const float* __restrict__ x, const float* __restrict__ W0,
                   const float* __restrict__ b0) {
    const int t = threadIdx.x;
    const int row0 = blockIdx.x * 16;
    float w[7];
#pragma unroll
    for (int k = 0; k < 7; k++) w[k] = W0[k * HID + t];
    float bb = b0[t];
    __shared__ float xs[16 * 8];
    for (int i = t; i < 16 * 7; i += 256) {
        int r = i / 7, c = i % 7;
        xs[r * 8 + c] = x[(size_t)(row0 + r) * 7 + c];
    }
    __syncthreads();
#pragma unroll
    for (int r = 0; r < 16; r++) {
        float acc = bb;
#pragma unroll
        for (int k = 0; k < 7; k++) acc += xs[r * 8 + k] * w[k];
        float s = silu(acc);
        bf16 h = __float2bfloat16(s);
        size_t o = (size_t)(row0 + r) * HID + t;
        g_a_hi[o] = h;
        g_a_lo[o] = __float2bfloat16(s - __bfloat162float(h));
    }
}

// ---------------- staging: 4 tiles of 128 rows x 32 bf16, SW64 swizzle ----------------
__device__ __forceinline__ void stage_issue(
    uint32_t sbu, int s, int kc,
    const bf16* __restrict__ Ahi, const bf16* __restrict__ Alo,
    const bf16* __restrict__ Bhi, const bf16* __restrict__ Blo, int t)
{
    const uint32_t st = sbu + s * STAGE_B;
#pragma unroll
    for (int half = 0; half < 2; half++) {
        int ch = t + half * 256;               // 0..511
        int r = ch >> 2, c = ch & 3;           // row, 16B chunk
        size_t g = (size_t)r * HID + kc * 32 + c * 8;
        uint32_t sw = sw64((uint32_t)(r * 64 + c * 16));
        cp16s(st + 0 * TILE_B + sw, Ahi + g);
        cp16s(st + 1 * TILE_B + sw, Alo + g);
        cp16s(st + 2 * TILE_B + sw, Bhi + g);
        cp16s(st + 3 * TILE_B + sw, Blo + g);
    }
    cp_commit();
}

// ---------------- per-stage compute ----------------
struct FragOffs {
    uint32_t a[2][2];   // [kk][mt]
    uint32_t b[2][4];   // [kk][np]
};

__device__ __forceinline__ void stage_compute(uint32_t sbu, int s,
                                              const FragOffs& fo,
                                              float acc[2][4][2][4])
{
    const uint32_t st = sbu + s * STAGE_B;
#pragma unroll
    for (int kk = 0; kk < 2; kk++) {
        uint32_t ah[2][4], al[2][4];
#pragma unroll
        for (int mt = 0; mt < 2; mt++) {
            ldsm4(ah[mt][0], ah[mt][1], ah[mt][2], ah[mt][3], st + 0 * TILE_B + fo.a[kk][mt]);
            ldsm4(al[mt][0], al[mt][1], al[mt][2], al[mt][3], st + 1 * TILE_B + fo.a[kk][mt]);
        }
#pragma unroll
        for (int np = 0; np < 4; np++) {
            uint32_t bh4[4], bl4[4];
            ldsm4(bh4[0], bh4[1], bh4[2], bh4[3], st + 2 * TILE_B + fo.b[kk][np]);
            ldsm4(bl4[0], bl4[1], bl4[2], bl4[3], st + 3 * TILE_B + fo.b[kk][np]);
            // term-outer ordering: same-acc reuse distance = 4 MMAs
#pragma unroll
            for (int mt = 0; mt < 2; mt++) {
                mma16816(acc[mt][np][0], ah[mt][0], ah[mt][1], ah[mt][2], ah[mt][3], bh4[0], bh4[2]);
                mma16816(acc[mt][np][1], ah[mt][0], ah[mt][1], ah[mt][2], ah[mt][3], bh4[1], bh4[3]);
            }
#pragma unroll
            for (int mt = 0; mt < 2; mt++) {
                mma16816(acc[mt][np][0], ah[mt][0], ah[mt][1], ah[mt][2], ah[mt][3], bl4[0], bl4[2]);
                mma16816(acc[mt][np][1], ah[mt][0], ah[mt][1], ah[mt][2], ah[mt][3], bl4[1], bl4[3]);
            }
#pragma unroll
            for (int mt = 0; mt < 2; mt++) {
                mma16816(acc[mt][np][0], al[mt][0], al[mt][1], al[mt][2], al[mt][3], bh4[0], bh4[2]);
                mma16816(acc[mt][np][1], al[mt][0], al[mt][1], al[mt][2], al[mt][3], bh4[1], bh4[3]);
            }
        }
    }
}

// ---------------- mainloop: 3-stage ring, 1 barrier per chunk ----------------
__device__ __forceinline__ void gemm_mainloop(
    uint32_t sbu,
    const bf16* __restrict__ Ahi, const bf16* __restrict__ Alo,
    const bf16* __restrict__ Bhi, const bf16* __restrict__ Blo,
    float acc[2][4][2][4], int t)
{
    const int lane = t & 31, warp = t >> 5, wm = warp & 3, wn = warp >> 2;
    FragOffs fo;
#pragma unroll
    for (int kk = 0; kk < 2; kk++) {
        uint32_t kb = kk * 32 + ((lane >> 4) << 4);
#pragma unroll
        for (int mt = 0; mt < 2; mt++)
            fo.a[kk][mt] = sw64((uint32_t)((wm * 32 + mt * 16 + (lane & 15)) * 64) + kb);
#pragma unroll
        for (int np = 0; np < 4; np++)
            fo.b[kk][np] = sw64((uint32_t)((wn * 64 + np * 16 + (lane & 15)) * 64) + kb);
    }

    stage_issue(sbu, 0, 0, Ahi, Alo, Bhi, Blo, t);
    stage_issue(sbu, 1, 1, Ahi, Alo, Bhi, Blo, t);

#pragma unroll
    for (int kc = 0; kc < 7; kc++) {
        cp_wait<1>();
        __syncthreads();
        if (kc < 6)
            stage_issue(sbu, (kc + 2) % 3, kc + 2, Ahi, Alo, Bhi, Blo, t);
        stage_compute(sbu, kc % 3, fo, acc);
    }
    cp_wait<0>();
    __syncthreads();
    stage_compute(sbu, 7 % 3, fo, acc);
}

// ---------------- hidden GEMM ----------------
template <int L>
__global__ __launch_bounds__(256, 2)
void gemm_hidden(const float* __restrict__ bias) {
    extern __shared__ __align__(16) char sm[];
    const uint32_t sbu = s2u(sm);

    const int t    = threadIdx.x;
    const int row0 = blockIdx.y * 128;
    const int nb0  = blockIdx.x * 128;

    const bf16* Ahi = (L == 1 ? g_b_hi : g_a_hi) + (size_t)row0 * HID;
    const bf16* Alo = (L == 1 ? g_b_lo : g_a_lo) + (size_t)row0 * HID;
    bf16* Ohi = (L == 1) ? g_a_hi : g_b_hi;
    bf16* Olo = (L == 1) ? g_a_lo : g_b_lo;
    const bf16* Bhi = g_w_hi + (size_t)L * HID * HID + (size_t)nb0 * HID;
    const bf16* Blo = g_w_lo + (size_t)L * HID * HID + (size_t)nb0 * HID;

    float acc[2][4][2][4];
#pragma unroll
    for (int a = 0; a < 2; a++)
#pragma unroll
        for (int b = 0; b < 4; b++)
#pragma unroll
            for (int c = 0; c < 2; c++)
#pragma unroll
                for (int d = 0; d < 4; d++) acc[a][b][c][d] = 0.f;

    gemm_mainloop(sbu, Ahi, Alo, Bhi, Blo, acc, t);

    const int lane = t & 31, warp = t >> 5, wm = warp & 3, wn = warp >> 2;
#pragma unroll
    for (int mt = 0; mt < 2; mt++) {
#pragma unroll
        for (int np = 0; np < 4; np++) {
#pragma unroll
            for (int sub = 0; sub < 2; sub++) {
                float* d = acc[mt][np][sub];
                int col = nb0 + wn * 64 + np * 16 + sub * 8 + (lane & 3) * 2;
                int r   = row0 + wm * 32 + mt * 16 + (lane >> 2);
                float bb0 = bias[col], bb1 = bias[col + 1];
                store_split(Ohi, Olo, (size_t)r * HID + col,
                            silu(d[0] + bb0), silu(d[1] + bb1));
                store_split(Ohi, Olo, (size_t)(r + 8) * HID + col,
                            silu(d[2] + bb0), silu(d[3] + bb1));
            }
        }
    }
}

// ---------------- head GEMM ----------------
__global__ __launch_bounds__(256, 2)
void gemm_head(const float* __restrict__ x, const float* __restrict__ bh,
               float* __restrict__ out) {
    extern __shared__ __align__(16) char sm[];
    const uint32_t sbu = s2u(sm);
    __shared__ float sL[128], sR[128], sN[128];

    const int t    = threadIdx.x;
    const int row0 = blockIdx.y * 128;
    const int nb0  = blockIdx.x * 128;

    if (t < 128) {
        float lam = x[(size_t)(row0 + t) * 7];
        float s   = 1.f / (1.f + __expf(-lam * (5.0f / 0.15f)));
        sL[t] = 1.f - s;
        sR[t] = s;
        sN[t] = __expf(-25.f * lam * lam);
    }

    const bf16* Ahi = g_b_hi + (size_t)row0 * HID;
    const bf16* Alo = g_b_lo + (size_t)row0 * HID;
    const bf16* Bhi = g_wh_hi + (size_t)nb0 * HID;
    const bf16* Blo = g_wh_lo + (size_t)nb0 * HID;

    float acc[2][4][2][4];
#pragma unroll
    for (int a = 0; a < 2; a++)
#pragma unroll
        for (int b = 0; b < 4; b++)
#pragma unroll
            for (int c = 0; c < 2; c++)
#pragma unroll
                for (int d = 0; d < 4; d++) acc[a][b][c][d] = 0.f;

    gemm_mainloop(sbu, Ahi, Alo, Bhi, Blo, acc, t);

    const int lane = t & 31, warp = t >> 5, wm = warp & 3, wn = warp >> 2;
#pragma unroll
    for (int mt = 0; mt < 2; mt++) {
#pragma unroll
        for (int np = 0; np < 4; np++) {
#pragma unroll
            for (int sub = 0; sub < 2; sub++) {
                float* d = acc[mt][np][sub];
                int col = nb0 + wn * 64 + np * 16 + sub * 8 + (lane & 3) * 2;
                int rl  = wm * 32 + mt * 16 + (lane >> 2);
                int rg  = row0 + rl;
                if (col < NCOL) {
                    float bb = bh[col];
                    int   h  = col / 35;
                    float s0 = (h < 35) ? 1.f : (h < 49) ? sL[rl]     : (h < 63) ? sR[rl]     : sN[rl];
                    float s1 = (h < 35) ? 1.f : (h < 49) ? sL[rl + 8] : (h < 63) ? sR[rl + 8] : sN[rl + 8];
                    out[(size_t)rg * NCOL + col]       = (d[0] + bb) * s0;
                    out[(size_t)(rg + 8) * NCOL + col] = (d[2] + bb) * s1;
                }
                int col1 = col + 1;
                if (col1 < NCOL) {
                    float bb = bh[col1];
                    int   h  = col1 / 35;
                    float s0 = (h < 35) ? 1.f : (h < 49) ? sL[rl]     : (h < 63) ? sR[rl]     : sN[rl];
                    float s1 = (h < 35) ? 1.f : (h < 49) ? sL[rl + 8] : (h < 63) ? sR[rl + 8] : sN[rl + 8];
                    out[(size_t)rg * NCOL + col1]       = (d[1] + bb) * s0;
                    out[(size_t)(rg + 8) * NCOL + col1] = (d[3] + bb) * s1;
                }
            }
        }
    }
}

// ---------------- launch ----------------
extern "C" void kernel_launch(void* const* d_in, const int* in_sizes, int n_in,
                              void* d_out, int out_size) {
    const float* x  = (const float*)d_in[0];
    const float* W0 = (const float*)d_in[1];
    const float* b0 = (const float*)d_in[2];
    const float* W1 = (const float*)d_in[3];
    const float* b1 = (const float*)d_in[4];
    const float* W2 = (const float*)d_in[5];
    const float* b2 = (const float*)d_in[6];
    const float* W3 = (const float*)d_in[7];
    const float* b3 = (const float*)d_in[8];
    const float* Wh = (const float*)d_in[9];
    const float* bh = (const float*)d_in[10];
    float* out = (float*)d_out;

    static bool attr_done = false;
    if (!attr_done) {
        cudaFuncSetAttribute(gemm_hidden<0>, cudaFuncAttributeMaxDynamicSharedMemorySize, DYN_BYTES);
        cudaFuncSetAttribute(gemm_hidden<1>, cudaFuncAttributeMaxDynamicSharedMemorySize, DYN_BYTES);
        cudaFuncSetAttribute(gemm_hidden<2>, cudaFuncAttributeMaxDynamicSharedMemorySize, DYN_BYTES);
        cudaFuncSetAttribute(gemm_head,      cudaFuncAttributeMaxDynamicSharedMemorySize, DYN_BYTES);
        attr_done = true;
    }

    prep_w_hidden<<<(3 * HID * HID + 255) / 256, 256>>>(W1, W2, W3);
    prep_w_head<<<(NPAD * HID + 255) / 256, 256>>>(Wh);
    layer0_kernel<<<BQ / 16, 256>>>(x, W0, b0);

    dim3 gh(HID / 128, BQ / 128);        // (2, 512), col tile fastest
    gemm_hidden<0><<<gh, 256, DYN_BYTES>>>(b1);   // a -> b
    gemm_hidden<1><<<gh, 256, DYN_BYTES>>>(b2);   // b -> a
    gemm_hidden<2><<<gh, 256, DYN_BYTES>>>(b3);   // a -> b

    dim3 gd(NPAD / 128, BQ / 128);       // (22, 512)
    gemm_head<<<gd, 256, DYN_BYTES>>>(x, bh, out);
}

// round 10
// speedup vs baseline: 6.6326x; 1.3608x over previous
#include <cuda_runtime.h>
#include <cuda_fp16.h>
#include <cstdint>

#define BQ   65536
#define HID  256
#define NCOL 2695
#define NPAD 2816                 // 22 * 128
#define TILE_B  8192              // 128 rows x 64B (32 fp16 of k), SW64-swizzled
#define STAGE_B (3 * TILE_B)      // A, Bhi, Blo = 24 KB
#define NSTAGE  3
#define DYN_BYTES (NSTAGE * STAGE_B)   // 72 KB

typedef __half fp16;

// ---------------- scratch ----------------
__device__ fp16 g_a[(size_t)BQ * HID];                          // act ping (33.5 MB)
__device__ fp16 g_b[(size_t)BQ * HID];                          // act pong
__device__ fp16 g_w_hi[3 * HID * HID], g_w_lo[3 * HID * HID];   // [l][n][k]
__device__ fp16 g_wh_hi[NPAD * HID],   g_wh_lo[NPAD * HID];     // [n][k], zero-padded

// ---------------- helpers ----------------
__device__ __forceinline__ uint32_t s2u(const void* p) {
    return (uint32_t)__cvta_generic_to_shared(p);
}
__device__ __forceinline__ void cp16s(uint32_t dst, const void* src) {
    asm volatile("cp.async.cg.shared.global [%0], [%1], 16;" :: "r"(dst), "l"(src));
}
__device__ __forceinline__ void cp_commit() { asm volatile("cp.async.commit_group;"); }
template <int N> __device__ __forceinline__ void cp_wait() {
    asm volatile("cp.async.wait_group %0;" :: "n"(N));
}
__device__ __forceinline__ void ldsm4(uint32_t& r0, uint32_t& r1, uint32_t& r2, uint32_t& r3,
                                      uint32_t addr) {
    asm volatile("ldmatrix.sync.aligned.m8n8.x4.shared.b16 {%0,%1,%2,%3}, [%4];"
                 : "=r"(r0), "=r"(r1), "=r"(r2), "=r"(r3) : "r"(addr));
}
__device__ __forceinline__ void mma16816(float* d,
                                         uint32_t a0, uint32_t a1, uint32_t a2, uint32_t a3,
                                         uint32_t b0, uint32_t b1) {
    asm volatile(
        "mma.sync.aligned.m16n8k16.row.col.f32.f16.f16.f32 "
        "{%0,%1,%2,%3},{%4,%5,%6,%7},{%8,%9},{%0,%1,%2,%3};"
        : "+f"(d[0]), "+f"(d[1]), "+f"(d[2]), "+f"(d[3])
        : "r"(a0), "r"(a1), "r"(a2), "r"(a3), "r"(b0), "r"(b1));
}
__device__ __forceinline__ float silu(float v) { return v / (1.f + __expf(-v)); }
__device__ __forceinline__ uint32_t sw64(uint32_t o) { return o ^ ((o >> 3) & 0x30); }

// ---------------- weight prep: fp16 hi/lo split, transposed [n][k] ----------------
__global__ void prep_w_hidden(const float* __restrict__ W1, const float* __restrict__ W2,
                              const float* __restrict__ W3) {
    int i = blockIdx.x * 256 + threadIdx.x;
    if (i >= 3 * HID * HID) return;
    int l = i >> 16, rem = i & 65535, n = rem >> 8, k = rem & 255;
    const float* W = (l == 0) ? W1 : (l == 1) ? W2 : W3;
    float v = W[k * HID + n];
    fp16 h = __float2half(v);
    g_w_hi[i] = h;
    g_w_lo[i] = __float2half(v - __half2float(h));
}
__global__ void prep_w_head(const float* __restrict__ Wh) {
    int i = blockIdx.x * 256 + threadIdx.x;
    if (i >= NPAD * HID) return;
    int n = i >> 8, k = i & 255;
    float v = (n < NCOL) ? Wh[k * NCOL + n] : 0.f;
    fp16 h = __float2half(v);
    g_wh_hi[i] = h;
    g_wh_lo[i] = __float2half(v - __half2float(h));
}

// ---------------- layer 0 : silu(x @ W0 + b0), K = 7 ----------------
__global__ __launch_bounds__(256)
void layer0_kernel(const float* __restrict__ x, const float* __restrict__ W0,
                   const float* __restrict__ b0) {
    const int t = threadIdx.x;
    const int row0 = blockIdx.x * 16;
    float w[7];
#pragma unroll
    for (int k = 0; k < 7; k++) w[k] = W0[k * HID + t];
    float bb = b0[t];
    __shared__ float xs[16 * 8];
    for (int i = t; i < 16 * 7; i += 256) {
        int r = i / 7, c = i % 7;
        xs[r * 8 + c] = x[(size_t)(row0 + r) * 7 + c];
    }
    __syncthreads();
#pragma unroll
    for (int r = 0; r < 16; r++) {
        float acc = bb;
#pragma unroll
        for (int k = 0; k < 7; k++) acc += xs[r * 8 + k] * w[k];
        g_a[(size_t)(row0 + r) * HID + t] = __float2half(silu(acc));
    }
}

// ---------------- staging: 3 tiles of 128 rows x 32 fp16, SW64 swizzle ----------------
__device__ __forceinline__ void stage_issue(
    uint32_t sbu, int s, int kc,
    const fp16* __restrict__ A,
    const fp16* __restrict__ Bhi, const fp16* __restrict__ Blo, int t)
{
    const uint32_t st = sbu + s * STAGE_B;
#pragma unroll
    for (int h = 0; h < 2; h++) {
        int ch = t + h * 256;                  // 0..511
        int r = ch >> 2, c = ch & 3;           // row, 16B chunk
        size_t g = (size_t)r * HID + kc * 32 + c * 8;
        uint32_t sw = sw64((uint32_t)(r * 64 + c * 16));
        cp16s(st + 0 * TILE_B + sw, A + g);
        cp16s(st + 1 * TILE_B + sw, Bhi + g);
        cp16s(st + 2 * TILE_B + sw, Blo + g);
    }
    cp_commit();
}

// ---------------- per-stage compute: 64 MMAs/warp ----------------
struct FragOffs {
    uint32_t a[2][2];   // [kk][mt]
    uint32_t b[2][4];   // [kk][np]
};

__device__ __forceinline__ void stage_compute(uint32_t sbu, int s,
                                              const FragOffs& fo,
                                              float acc[2][4][2][4])
{
    const uint32_t st = sbu + s * STAGE_B;
#pragma unroll
    for (int kk = 0; kk < 2; kk++) {
        uint32_t a[2][4];
#pragma unroll
        for (int mt = 0; mt < 2; mt++)
            ldsm4(a[mt][0], a[mt][1], a[mt][2], a[mt][3], st + 0 * TILE_B + fo.a[kk][mt]);
#pragma unroll
        for (int np = 0; np < 4; np++) {
            uint32_t bh4[4], bl4[4];
            ldsm4(bh4[0], bh4[1], bh4[2], bh4[3], st + 1 * TILE_B + fo.b[kk][np]);
            ldsm4(bl4[0], bl4[1], bl4[2], bl4[3], st + 2 * TILE_B + fo.b[kk][np]);
            // term-outer ordering: same-acc reuse distance = 4 MMAs
#pragma unroll
            for (int mt = 0; mt < 2; mt++) {
                mma16816(acc[mt][np][0], a[mt][0], a[mt][1], a[mt][2], a[mt][3], bh4[0], bh4[2]);
                mma16816(acc[mt][np][1], a[mt][0], a[mt][1], a[mt][2], a[mt][3], bh4[1], bh4[3]);
            }
#pragma unroll
            for (int mt = 0; mt < 2; mt++) {
                mma16816(acc[mt][np][0], a[mt][0], a[mt][1], a[mt][2], a[mt][3], bl4[0], bl4[2]);
                mma16816(acc[mt][np][1], a[mt][0], a[mt][1], a[mt][2], a[mt][3], bl4[1], bl4[3]);
            }
        }
    }
}

// ---------------- mainloop: 3-stage ring, 1 barrier per chunk ----------------
__device__ __forceinline__ void gemm_mainloop(
    uint32_t sbu,
    const fp16* __restrict__ A,
    const fp16* __restrict__ Bhi, const fp16* __restrict__ Blo,
    float acc[2][4][2][4], int t)
{
    const int lane = t & 31, warp = t >> 5, wm = warp & 3, wn = warp >> 2;
    FragOffs fo;
#pragma unroll
    for (int kk = 0; kk < 2; kk++) {
        uint32_t kb = kk * 32 + ((lane >> 4) << 4);
#pragma unroll
        for (int mt = 0; mt < 2; mt++)
            fo.a[kk][mt] = sw64((uint32_t)((wm * 32 + mt * 16 + (lane & 15)) * 64) + kb);
#pragma unroll
        for (int np = 0; np < 4; np++)
            fo.b[kk][np] = sw64((uint32_t)((wn * 64 + np * 16 + (lane & 15)) * 64) + kb);
    }

    stage_issue(sbu, 0, 0, A, Bhi, Blo, t);
    stage_issue(sbu, 1, 1, A, Bhi, Blo, t);

#pragma unroll
    for (int kc = 0; kc < 7; kc++) {
        cp_wait<1>();
        __syncthreads();
        if (kc < 6)
            stage_issue(sbu, (kc + 2) % 3, kc + 2, A, Bhi, Blo, t);
        stage_compute(sbu, kc % 3, fo, acc);
    }
    cp_wait<0>();
    __syncthreads();
    stage_compute(sbu, 7 % 3, fo, acc);
}

// ---------------- hidden GEMM ----------------
template <int L>
__global__ __launch_bounds__(256, 2)
void gemm_hidden(const float* __restrict__ bias) {
    extern __shared__ __align__(16) char sm[];
    const uint32_t sbu = s2u(sm);

    const int t    = threadIdx.x;
    const int row0 = blockIdx.y * 128;
    const int nb0  = blockIdx.x * 128;

    const fp16* A = (L == 1 ? g_b : g_a) + (size_t)row0 * HID;
    fp16* O = (L == 1) ? g_a : g_b;
    const fp16* Bhi = g_w_hi + (size_t)L * HID * HID + (size_t)nb0 * HID;
    const fp16* Blo = g_w_lo + (size_t)L * HID * HID + (size_t)nb0 * HID;

    float acc[2][4][2][4];
#pragma unroll
    for (int a = 0; a < 2; a++)
#pragma unroll
        for (int b = 0; b < 4; b++)
#pragma unroll
            for (int c = 0; c < 2; c++)
#pragma unroll
                for (int d = 0; d < 4; d++) acc[a][b][c][d] = 0.f;

    gemm_mainloop(sbu, A, Bhi, Blo, acc, t);

    const int lane = t & 31, warp = t >> 5, wm = warp & 3, wn = warp >> 2;
#pragma unroll
    for (int mt = 0; mt < 2; mt++) {
#pragma unroll
        for (int np = 0; np < 4; np++) {
#pragma unroll
            for (int sub = 0; sub < 2; sub++) {
                float* d = acc[mt][np][sub];
                int col = nb0 + wn * 64 + np * 16 + sub * 8 + (lane & 3) * 2;
                int r   = row0 + wm * 32 + mt * 16 + (lane >> 2);
                float bb0 = bias[col], bb1 = bias[col + 1];
                __half2 v0; v0.x = __float2half(silu(d[0] + bb0));
                            v0.y = __float2half(silu(d[1] + bb1));
                *(__half2*)(O + (size_t)r * HID + col) = v0;
                __half2 v1; v1.x = __float2half(silu(d[2] + bb0));
                            v1.y = __float2half(silu(d[3] + bb1));
                *(__half2*)(O + (size_t)(r + 8) * HID + col) = v1;
            }
        }
    }
}

// ---------------- head GEMM ----------------
__global__ __launch_bounds__(256, 2)
void gemm_head(const float* __restrict__ x, const float* __restrict__ bh,
               float* __restrict__ out) {
    extern __shared__ __align__(16) char sm[];
    const uint32_t sbu = s2u(sm);
    __shared__ float sL[128], sR[128], sN[128];

    const int t    = threadIdx.x;
    const int row0 = blockIdx.y * 128;
    const int nb0  = blockIdx.x * 128;

    if (t < 128) {
        float lam = x[(size_t)(row0 + t) * 7];
        float s   = 1.f / (1.f + __expf(-lam * (5.0f / 0.15f)));
        sL[t] = 1.f - s;
        sR[t] = s;
        sN[t] = __expf(-25.f * lam * lam);
    }

    const fp16* A   = g_b + (size_t)row0 * HID;
    const fp16* Bhi = g_wh_hi + (size_t)nb0 * HID;
    const fp16* Blo = g_wh_lo + (size_t)nb0 * HID;

    float acc[2][4][2][4];
#pragma unroll
    for (int a = 0; a < 2; a++)
#pragma unroll
        for (int b = 0; b < 4; b++)
#pragma unroll
            for (int c = 0; c < 2; c++)
#pragma unroll
                for (int d = 0; d < 4; d++) acc[a][b][c][d] = 0.f;

    gemm_mainloop(sbu, A, Bhi, Blo, acc, t);

    const int lane = t & 31, warp = t >> 5, wm = warp & 3, wn = warp >> 2;
#pragma unroll
    for (int mt = 0; mt < 2; mt++) {
#pragma unroll
        for (int np = 0; np < 4; np++) {
#pragma unroll
            for (int sub = 0; sub < 2; sub++) {
                float* d = acc[mt][np][sub];
                int col = nb0 + wn * 64 + np * 16 + sub * 8 + (lane & 3) * 2;
                int rl  = wm * 32 + mt * 16 + (lane >> 2);
                int rg  = row0 + rl;
                if (col < NCOL) {
                    float bb = bh[col];
                    int   h  = col / 35;
                    float s0 = (h < 35) ? 1.f : (h < 49) ? sL[rl]     : (h < 63) ? sR[rl]     : sN[rl];
                    float s1 = (h < 35) ? 1.f : (h < 49) ? sL[rl + 8] : (h < 63) ? sR[rl + 8] : sN[rl + 8];
                    out[(size_t)rg * NCOL + col]       = (d[0] + bb) * s0;
                    out[(size_t)(rg + 8) * NCOL + col] = (d[2] + bb) * s1;
                }
                int col1 = col + 1;
                if (col1 < NCOL) {
                    float bb = bh[col1];
                    int   h  = col1 / 35;
                    float s0 = (h < 35) ? 1.f : (h < 49) ? sL[rl]     : (h < 63) ? sR[rl]     : sN[rl];
                    float s1 = (h < 35) ? 1.f : (h < 49) ? sL[rl + 8] : (h < 63) ? sR[rl + 8] : sN[rl + 8];
                    out[(size_t)rg * NCOL + col1]       = (d[1] + bb) * s0;
                    out[(size_t)(rg + 8) * NCOL + col1] = (d[3] + bb) * s1;
                }
            }
        }
    }
}

// ---------------- launch ----------------
extern "C" void kernel_launch(void* const* d_in, const int* in_sizes, int n_in,
                              void* d_out, int out_size) {
    const float* x  = (const float*)d_in[0];
    const float* W0 = (const float*)d_in[1];
    const float* b0 = (const float*)d_in[2];
    const float* W1 = (const float*)d_in[3];
    const float* b1 = (const float*)d_in[4];
    const float* W2 = (const float*)d_in[5];
    const float* b2 = (const float*)d_in[6];
    const float* W3 = (const float*)d_in[7];
    const float* b3 = (const float*)d_in[8];
    const float* Wh = (const float*)d_in[9];
    const float* bh = (const float*)d_in[10];
    float* out = (float*)d_out;

    static bool attr_done = false;
    if (!attr_done) {
        cudaFuncSetAttribute(gemm_hidden<0>, cudaFuncAttributeMaxDynamicSharedMemorySize, DYN_BYTES);
        cudaFuncSetAttribute(gemm_hidden<1>, cudaFuncAttributeMaxDynamicSharedMemorySize, DYN_BYTES);
        cudaFuncSetAttribute(gemm_hidden<2>, cudaFuncAttributeMaxDynamicSharedMemorySize, DYN_BYTES);
        cudaFuncSetAttribute(gemm_head,      cudaFuncAttributeMaxDynamicSharedMemorySize, DYN_BYTES);
        attr_done = true;
    }

    prep_w_hidden<<<(3 * HID * HID + 255) / 256, 256>>>(W1, W2, W3);
    prep_w_head<<<(NPAD * HID + 255) / 256, 256>>>(Wh);
    layer0_kernel<<<BQ / 16, 256>>>(x, W0, b0);

    dim3 gh(HID / 128, BQ / 128);        // (2, 512)
    gemm_hidden<0><<<gh, 256, DYN_BYTES>>>(b1);   // a -> b
    gemm_hidden<1><<<gh, 256, DYN_BYTES>>>(b2);   // b -> a
    gemm_hidden<2><<<gh, 256, DYN_BYTES>>>(b3);   // a -> b

    dim3 gd(NPAD / 128, BQ / 128);       // (22, 512)
    gemm_head<<<gd, 256, DYN_BYTES>>>(x, bh, out);
}